// round 11
// baseline (speedup 1.0000x reference)
#include <cuda_runtime.h>
#include <cstdint>

#define VOCAB 81616
#define DIM 32
#define BATCH 4096

typedef unsigned long long u64;

// ---------------- pass 1 config: BM=128, 4 warps, 4 CTAs/SM ----------------
#define BM 128
#define BK 32
#define NSPLIT 18
#define NTILES ((VOCAB + BK - 1) / BK)        // 2551
#define TPS ((NTILES + NSPLIT - 1) / NSPLIT)  // 142
#define ROWBLOCKS (BATCH / BM)                // 32
#define P1_THREADS 128

#define XS_STRIDE 36                          // 144B rows: 16B-aligned, bank=4r+c
#define P1_XS_BYTES (BM * XS_STRIDE * 4)      // 18432
#define P1_WS_BYTES (BK * XS_STRIDE * 4)      // 4608
#define P1_BUF (P1_XS_BYTES + P1_WS_BYTES)    // 23040
#define P1_SMEM (2 * P1_BUF)                  // 46080 -> 4 CTAs/SM (184KB/227KB)

// ---------------- pass 2 config ----------------
#define P2_THREADS 256
#define P2_MROWS 64
#define P2_COLS 128
#define P2_YSPLIT 4
#define P2_CHUNKS ((BATCH / P2_YSPLIT) / P2_MROWS)  // 16
#define HS_STRIDE 36

// Scratch (no cudaMalloc allowed — device globals)
__device__ __align__(16) float g_partial[NSPLIT * BATCH * DIM];  // 9.4 MB
__device__ __align__(16) float g_h[BATCH * DIM];                 // 512 KB (tf32-rounded)

// ---------------- helpers ----------------
__device__ __forceinline__ float sigt(float x) {
    float t;
    asm("tanh.approx.f32 %0, %1;" : "=f"(t) : "f"(x * 0.5f));
    return fmaf(0.5f, t, 0.5f);
}

__device__ __forceinline__ unsigned smem_u32(const void* p) {
    unsigned a;
    asm("{ .reg .u64 t; cvta.to.shared.u64 t, %1; cvt.u32.u64 %0, t; }" : "=r"(a) : "l"(p));
    return a;
}

__device__ __forceinline__ void cp16z(unsigned dst, const void* src, unsigned sz) {
    asm volatile("cp.async.cg.shared.global [%0], [%1], 16, %2;" :: "r"(dst), "l"(src), "r"(sz));
}
__device__ __forceinline__ void cp4(unsigned dst, const void* src, unsigned sz) {
    asm volatile("cp.async.ca.shared.global [%0], [%1], 4, %2;" :: "r"(dst), "l"(src), "r"(sz));
}
__device__ __forceinline__ void cp16(unsigned dst, const void* src) {
    asm volatile("cp.async.ca.shared.global [%0], [%1], 16;" :: "r"(dst), "l"(src));
}
#define CP_COMMIT() asm volatile("cp.async.commit_group;")
#define CP_WAIT1()  asm volatile("cp.async.wait_group 1;")

__device__ __forceinline__ uint32_t to_tf32(float f) {
    uint32_t r;
    asm("cvt.rna.tf32.f32 %0, %1;" : "=r"(r) : "f"(f));
    return r;
}

__device__ __forceinline__ void mma_tf32(float* d, const uint32_t* a, const uint32_t* b) {
    asm("mma.sync.aligned.m16n8k8.row.col.f32.tf32.tf32.f32 "
        "{%0,%1,%2,%3}, {%4,%5,%6,%7}, {%8,%9}, {%0,%1,%2,%3};"
        : "+f"(d[0]), "+f"(d[1]), "+f"(d[2]), "+f"(d[3])
        : "r"(a[0]), "r"(a[1]), "r"(a[2]), "r"(a[3]), "r"(b[0]), "r"(b[1]));
}

// =====================================================================
// Pass 1 (tf32 tensor): partial[s] = x[rows] @ w over this split's chunk.
// BM=128, 128 thr = 4 warps (warp: 32 rows x 32 cols, 2 mt x 4 nt,
// acc=32). Same 16 warps/SM as the 259us config, but split over 4
// independent CTAs -> load/compute phases of different CTAs interleave
// across the per-tile wait+syncthreads bubbles. Grid = 576 = one wave.
// =====================================================================
__device__ __forceinline__ void p1_load(unsigned sb, int buf, int tile,
                                        const float* __restrict__ X,
                                        const float* __restrict__ W,
                                        int row0, int t) {
    const int k0 = tile * BK;
    const unsigned xbase = sb + (unsigned)buf * P1_BUF;
    const unsigned wbase = xbase + P1_XS_BYTES;

    // x: 128 rows x 8 float4 -> 8 cp16 per thread; lanes 0..7 cover one row
    const int u  = t & 7;              // float4 index within row (cols 4u..4u+3)
    const int r0 = t >> 3;             // 0..15
    const int gk = k0 + 4 * u;
    const unsigned szx = (gk < VOCAB) ? 16u : 0u;  // VOCAB%4==0 -> all-or-none
    const float* srcx = (gk < VOCAB) ? (X + (size_t)(row0 + r0) * VOCAB + gk) : X;
#pragma unroll
    for (int i = 0; i < 8; ++i) {
        int row = i * 16 + r0;
        cp16z(xbase + (unsigned)(row * XS_STRIDE + 4 * u) * 4u, srcx, szx);
        srcx += (size_t)16 * VOCAB;
    }

    // w: 32 k-rows x 32 j, native layout ws[k][j]; 8 cp4 per thread
    const int j  = t & 31;
    const int kb = t >> 5;             // 0..3
#pragma unroll
    for (int i = 0; i < 8; ++i) {
        int kk = kb + i * 4;
        int g  = k0 + kk;
        unsigned sz = (g < VOCAB) ? 4u : 0u;
        const float* src = (g < VOCAB) ? (W + (size_t)g * DIM + j) : W;
        cp4(wbase + (unsigned)(kk * XS_STRIDE + j) * 4u, src, sz);
    }
}

__global__ __launch_bounds__(P1_THREADS, 4) void pass1_kernel(const float* __restrict__ X,
                                                              const float* __restrict__ W) {
    extern __shared__ char smem[];
    const unsigned sb = smem_u32(smem);

    const int t    = threadIdx.x;
    const int lane = t & 31;
    const int wid  = t >> 5;           // 0..3 -> m-slab
    const int g    = lane >> 2;
    const int tig  = lane & 3;
    const int row0 = blockIdx.x * BM;
    const int s    = blockIdx.y;

    float acc[32];
#pragma unroll
    for (int i = 0; i < 32; ++i) acc[i] = 0.f;

    const int tile0 = s * TPS;
    const int tile1 = (tile0 + TPS < NTILES) ? (tile0 + TPS) : NTILES;
    const int nt_   = tile1 - tile0;

    p1_load(sb, 0, tile0, X, W, row0, t);
    CP_COMMIT();

    const int mrow = wid * 32 + g;

    for (int i = 0; i < nt_; ++i) {
        if (i + 1 < nt_) p1_load(sb, (i + 1) & 1, tile0 + i + 1, X, W, row0, t);
        CP_COMMIT();
        CP_WAIT1();
        __syncthreads();

        const float* xp = reinterpret_cast<const float*>(smem + (i & 1) * P1_BUF);
        const float* wp = reinterpret_cast<const float*>(smem + (i & 1) * P1_BUF + P1_XS_BYTES);

#pragma unroll
        for (int ks = 0; ks < 4; ++ks) {
            const int kc = ks * 8;
            uint32_t a[2][4], b[4][2];
#pragma unroll
            for (int mt = 0; mt < 2; ++mt) {
                const float* ap = xp + (mrow + mt * 16) * XS_STRIDE + kc + tig;
                a[mt][0] = to_tf32(ap[0]);
                a[mt][1] = to_tf32(ap[8 * XS_STRIDE]);
                a[mt][2] = to_tf32(ap[4]);
                a[mt][3] = to_tf32(ap[8 * XS_STRIDE + 4]);
            }
#pragma unroll
            for (int nt2 = 0; nt2 < 4; ++nt2) {
                const float* bp = wp + (kc + tig) * XS_STRIDE + nt2 * 8 + g;
                b[nt2][0] = to_tf32(bp[0]);
                b[nt2][1] = to_tf32(bp[4 * XS_STRIDE]);
            }
#pragma unroll
            for (int mt = 0; mt < 2; ++mt)
#pragma unroll
                for (int nt2 = 0; nt2 < 4; ++nt2)
                    mma_tf32(&acc[(mt * 4 + nt2) * 4], a[mt], b[nt2]);
        }
        __syncthreads();
    }

#pragma unroll
    for (int mt = 0; mt < 2; ++mt) {
#pragma unroll
        for (int nt2 = 0; nt2 < 4; ++nt2) {
            const float* d = &acc[(mt * 4 + nt2) * 4];
            int r = row0 + mrow + mt * 16;
            int c = nt2 * 8 + 2 * tig;
            float2 lo = make_float2(d[0], d[1]);
            float2 hi = make_float2(d[2], d[3]);
            *reinterpret_cast<float2*>(&g_partial[((size_t)s * BATCH + r) * DIM + c]) = lo;
            *reinterpret_cast<float2*>(&g_partial[((size_t)s * BATCH + r + 8) * DIM + c]) = hi;
        }
    }
}

// =====================================================================
// Reduce partials + bias + sigmoid -> g_h (tf32-pre-rounded for pass2)
// =====================================================================
__global__ void reduce_act_kernel(const float* __restrict__ b) {
    int idx = blockIdx.x * blockDim.x + threadIdx.x;
    if (idx >= BATCH * DIM) return;
    float sum = b[idx & (DIM - 1)];
#pragma unroll
    for (int s = 0; s < NSPLIT; ++s)
        sum += g_partial[(size_t)s * BATCH * DIM + idx];
    g_h[idx] = __uint_as_float(to_tf32(sigt(sum)));
}

// =====================================================================
// Pass 2 (tf32 tensor): y = sigmoid(h @ w^T)  [round-7 passing version]
// =====================================================================
__device__ __forceinline__ void p2_load(unsigned hbase, int buf, int ib, int t) {
    const unsigned dst0 = hbase + (unsigned)buf * (P2_MROWS * HS_STRIDE * 4);
#pragma unroll
    for (int i = 0; i < 2; ++i) {
        int e   = i * P2_THREADS + t;
        int row = e >> 3;
        int q   = e & 7;
        cp16(dst0 + (unsigned)(row * HS_STRIDE + q * 4) * 4u,
             &g_h[(size_t)(ib + row) * DIM + q * 4]);
    }
}

__global__ __launch_bounds__(P2_THREADS, 2) void pass2_kernel(const float* __restrict__ W,
                                                              float* __restrict__ Y) {
    __shared__ float hs[2][P2_MROWS * HS_STRIDE];
    const unsigned hbase = smem_u32(&hs[0][0]);

    const int t    = threadIdx.x;
    const int lane = t & 31;
    const int wid  = t >> 5;
    const int wm   = wid & 3;
    const int wn   = wid >> 2;
    const int g    = lane >> 2;
    const int tig  = lane & 3;
    const int c0   = blockIdx.x * P2_COLS + wn * 64;
    const int ib0  = blockIdx.y * (BATCH / P2_YSPLIT);

    uint32_t bw[8][4][2];
#pragma unroll
    for (int nt = 0; nt < 8; ++nt) {
        int j = c0 + nt * 8 + g;
        bool v = (j < VOCAB);
        const float* wr = W + (size_t)(v ? j : 0) * DIM;
#pragma unroll
        for (int ks = 0; ks < 4; ++ks) {
            bw[nt][ks][0] = to_tf32(v ? wr[ks * 8 + tig]     : 0.f);
            bw[nt][ks][1] = to_tf32(v ? wr[ks * 8 + tig + 4] : 0.f);
        }
    }

    p2_load(hbase, 0, ib0, t);
    CP_COMMIT();

    for (int c = 0; c < P2_CHUNKS; ++c) {
        if (c + 1 < P2_CHUNKS) p2_load(hbase, (c + 1) & 1, ib0 + (c + 1) * P2_MROWS, t);
        CP_COMMIT();
        CP_WAIT1();
        __syncthreads();

        const float* hb = hs[c & 1];
        float acc[8][4];
#pragma unroll
        for (int nt = 0; nt < 8; ++nt)
#pragma unroll
            for (int i = 0; i < 4; ++i) acc[nt][i] = 0.f;

#pragma unroll
        for (int ks = 0; ks < 4; ++ks) {
            uint32_t a[4];
            const float* ap = hb + (wm * 16 + g) * HS_STRIDE + ks * 8 + tig;
            a[0] = __float_as_uint(ap[0]);
            a[1] = __float_as_uint(ap[8 * HS_STRIDE]);
            a[2] = __float_as_uint(ap[4]);
            a[3] = __float_as_uint(ap[8 * HS_STRIDE + 4]);
#pragma unroll
            for (int nt = 0; nt < 8; ++nt)
                mma_tf32(acc[nt], a, bw[nt][ks]);
        }

        const size_t r0 = (size_t)(ib0 + c * P2_MROWS + wm * 16 + g);
#pragma unroll
        for (int nt = 0; nt < 8; ++nt) {
            int colb = c0 + nt * 8;
            if (colb < VOCAB) {
                int col = colb + 2 * tig;
                float2 lo = make_float2(sigt(acc[nt][0]), sigt(acc[nt][1]));
                float2 hi = make_float2(sigt(acc[nt][2]), sigt(acc[nt][3]));
                *reinterpret_cast<float2*>(&Y[r0 * VOCAB + col])       = lo;
                *reinterpret_cast<float2*>(&Y[(r0 + 8) * VOCAB + col]) = hi;
            }
        }
        __syncthreads();
    }
}

// =====================================================================
extern "C" void kernel_launch(void* const* d_in, const int* in_sizes, int n_in,
                              void* d_out, int out_size) {
    const float* x = (const float*)d_in[0];  // [4096, 81616]
    const float* w = (const float*)d_in[1];  // [81616, 32]
    const float* b = (const float*)d_in[2];  // [32]
    float* y = (float*)d_out;                // [4096, 81616]

    cudaFuncSetAttribute(pass1_kernel, cudaFuncAttributeMaxDynamicSharedMemorySize, P1_SMEM);

    dim3 g1(ROWBLOCKS, NSPLIT);
    pass1_kernel<<<g1, P1_THREADS, P1_SMEM>>>(x, w);

    reduce_act_kernel<<<(BATCH * DIM + 255) / 256, 256>>>(b);

    dim3 g2((VOCAB + P2_COLS - 1) / P2_COLS, P2_YSPLIT);
    pass2_kernel<<<g2, P2_THREADS>>>(w, y);
}

// round 12
// speedup vs baseline: 1.0241x; 1.0241x over previous
#include <cuda_runtime.h>
#include <cstdint>

#define VOCAB 81616
#define DIM 32
#define BATCH 4096

typedef unsigned long long u64;

// ---------------- pass 1 config: BM=128, 4 warps, 4 CTAs/SM ----------------
#define BM 128
#define BK 32
#define NSPLIT 18
#define NTILES ((VOCAB + BK - 1) / BK)        // 2551
#define TPS ((NTILES + NSPLIT - 1) / NSPLIT)  // 142
#define ROWBLOCKS (BATCH / BM)                // 32
#define P1_THREADS 128

#define XS_STRIDE 36                          // 144B rows: 16B-aligned, bank=4r+c
#define P1_XS_BYTES (BM * XS_STRIDE * 4)      // 18432
#define P1_WS_BYTES (BK * XS_STRIDE * 4)      // 4608
#define P1_BUF (P1_XS_BYTES + P1_WS_BYTES)    // 23040
#define P1_SMEM (2 * P1_BUF)                  // 46080 -> 4 CTAs/SM (184KB/227KB)

// ---------------- pass 2 config ----------------
#define P2_THREADS 256
#define P2_MROWS 64
#define P2_COLS 128
#define P2_YSPLIT 4
#define P2_CHUNKS ((BATCH / P2_YSPLIT) / P2_MROWS)  // 16
#define HS_STRIDE 36

// Scratch (no cudaMalloc allowed — device globals)
__device__ __align__(16) float g_partial[NSPLIT * BATCH * DIM];  // 9.4 MB
__device__ __align__(16) float g_h[BATCH * DIM];                 // 512 KB (tf32-rounded)

// ---------------- helpers ----------------
__device__ __forceinline__ float sigt(float x) {
    float t;
    asm("tanh.approx.f32 %0, %1;" : "=f"(t) : "f"(x * 0.5f));
    return fmaf(0.5f, t, 0.5f);
}

__device__ __forceinline__ unsigned smem_u32(const void* p) {
    unsigned a;
    asm("{ .reg .u64 t; cvta.to.shared.u64 t, %1; cvt.u32.u64 %0, t; }" : "=r"(a) : "l"(p));
    return a;
}

__device__ __forceinline__ void cp16z(unsigned dst, const void* src, unsigned sz) {
    asm volatile("cp.async.cg.shared.global [%0], [%1], 16, %2;" :: "r"(dst), "l"(src), "r"(sz));
}
__device__ __forceinline__ void cp4(unsigned dst, const void* src, unsigned sz) {
    asm volatile("cp.async.ca.shared.global [%0], [%1], 4, %2;" :: "r"(dst), "l"(src), "r"(sz));
}
__device__ __forceinline__ void cp16(unsigned dst, const void* src) {
    asm volatile("cp.async.ca.shared.global [%0], [%1], 16;" :: "r"(dst), "l"(src));
}
#define CP_COMMIT() asm volatile("cp.async.commit_group;")
#define CP_WAIT1()  asm volatile("cp.async.wait_group 1;")

__device__ __forceinline__ uint32_t to_tf32(float f) {
    uint32_t r;
    asm("cvt.rna.tf32.f32 %0, %1;" : "=r"(r) : "f"(f));
    return r;
}

__device__ __forceinline__ void mma_tf32(float* d, const uint32_t* a, const uint32_t* b) {
    asm("mma.sync.aligned.m16n8k8.row.col.f32.tf32.tf32.f32 "
        "{%0,%1,%2,%3}, {%4,%5,%6,%7}, {%8,%9}, {%0,%1,%2,%3};"
        : "+f"(d[0]), "+f"(d[1]), "+f"(d[2]), "+f"(d[3])
        : "r"(a[0]), "r"(a[1]), "r"(a[2]), "r"(a[3]), "r"(b[0]), "r"(b[1]));
}

// =====================================================================
// Pass 1 (tf32 tensor): partial[s] = x[rows] @ w over this split's chunk.
// BM=128, 128 thr = 4 warps (warp: 32 rows x 32 cols, 2 mt x 4 nt,
// acc=32). Same 16 warps/SM as the 259us config, but split over 4
// independent CTAs -> load/compute phases of different CTAs interleave
// across the per-tile wait+syncthreads bubbles. Grid = 576 = one wave.
// =====================================================================
__device__ __forceinline__ void p1_load(unsigned sb, int buf, int tile,
                                        const float* __restrict__ X,
                                        const float* __restrict__ W,
                                        int row0, int t) {
    const int k0 = tile * BK;
    const unsigned xbase = sb + (unsigned)buf * P1_BUF;
    const unsigned wbase = xbase + P1_XS_BYTES;

    // x: 128 rows x 8 float4 -> 8 cp16 per thread; lanes 0..7 cover one row
    const int u  = t & 7;              // float4 index within row (cols 4u..4u+3)
    const int r0 = t >> 3;             // 0..15
    const int gk = k0 + 4 * u;
    const unsigned szx = (gk < VOCAB) ? 16u : 0u;  // VOCAB%4==0 -> all-or-none
    const float* srcx = (gk < VOCAB) ? (X + (size_t)(row0 + r0) * VOCAB + gk) : X;
#pragma unroll
    for (int i = 0; i < 8; ++i) {
        int row = i * 16 + r0;
        cp16z(xbase + (unsigned)(row * XS_STRIDE + 4 * u) * 4u, srcx, szx);
        srcx += (size_t)16 * VOCAB;
    }

    // w: 32 k-rows x 32 j, native layout ws[k][j]; 8 cp4 per thread
    const int j  = t & 31;
    const int kb = t >> 5;             // 0..3
#pragma unroll
    for (int i = 0; i < 8; ++i) {
        int kk = kb + i * 4;
        int g  = k0 + kk;
        unsigned sz = (g < VOCAB) ? 4u : 0u;
        const float* src = (g < VOCAB) ? (W + (size_t)g * DIM + j) : W;
        cp4(wbase + (unsigned)(kk * XS_STRIDE + j) * 4u, src, sz);
    }
}

__global__ __launch_bounds__(P1_THREADS, 4) void pass1_kernel(const float* __restrict__ X,
                                                              const float* __restrict__ W) {
    extern __shared__ char smem[];
    const unsigned sb = smem_u32(smem);

    const int t    = threadIdx.x;
    const int lane = t & 31;
    const int wid  = t >> 5;           // 0..3 -> m-slab
    const int g    = lane >> 2;
    const int tig  = lane & 3;
    const int row0 = blockIdx.x * BM;
    const int s    = blockIdx.y;

    float acc[32];
#pragma unroll
    for (int i = 0; i < 32; ++i) acc[i] = 0.f;

    const int tile0 = s * TPS;
    const int tile1 = (tile0 + TPS < NTILES) ? (tile0 + TPS) : NTILES;
    const int nt_   = tile1 - tile0;

    p1_load(sb, 0, tile0, X, W, row0, t);
    CP_COMMIT();

    const int mrow = wid * 32 + g;

    for (int i = 0; i < nt_; ++i) {
        if (i + 1 < nt_) p1_load(sb, (i + 1) & 1, tile0 + i + 1, X, W, row0, t);
        CP_COMMIT();
        CP_WAIT1();
        __syncthreads();

        const float* xp = reinterpret_cast<const float*>(smem + (i & 1) * P1_BUF);
        const float* wp = reinterpret_cast<const float*>(smem + (i & 1) * P1_BUF + P1_XS_BYTES);

#pragma unroll
        for (int ks = 0; ks < 4; ++ks) {
            const int kc = ks * 8;
            uint32_t a[2][4], b[4][2];
#pragma unroll
            for (int mt = 0; mt < 2; ++mt) {
                const float* ap = xp + (mrow + mt * 16) * XS_STRIDE + kc + tig;
                a[mt][0] = to_tf32(ap[0]);
                a[mt][1] = to_tf32(ap[8 * XS_STRIDE]);
                a[mt][2] = to_tf32(ap[4]);
                a[mt][3] = to_tf32(ap[8 * XS_STRIDE + 4]);
            }
#pragma unroll
            for (int nt2 = 0; nt2 < 4; ++nt2) {
                const float* bp = wp + (kc + tig) * XS_STRIDE + nt2 * 8 + g;
                b[nt2][0] = to_tf32(bp[0]);
                b[nt2][1] = to_tf32(bp[4 * XS_STRIDE]);
            }
#pragma unroll
            for (int mt = 0; mt < 2; ++mt)
#pragma unroll
                for (int nt2 = 0; nt2 < 4; ++nt2)
                    mma_tf32(&acc[(mt * 4 + nt2) * 4], a[mt], b[nt2]);
        }
        __syncthreads();
    }

#pragma unroll
    for (int mt = 0; mt < 2; ++mt) {
#pragma unroll
        for (int nt2 = 0; nt2 < 4; ++nt2) {
            const float* d = &acc[(mt * 4 + nt2) * 4];
            int r = row0 + mrow + mt * 16;
            int c = nt2 * 8 + 2 * tig;
            float2 lo = make_float2(d[0], d[1]);
            float2 hi = make_float2(d[2], d[3]);
            *reinterpret_cast<float2*>(&g_partial[((size_t)s * BATCH + r) * DIM + c]) = lo;
            *reinterpret_cast<float2*>(&g_partial[((size_t)s * BATCH + r + 8) * DIM + c]) = hi;
        }
    }
}

// =====================================================================
// Reduce partials + bias + sigmoid -> g_h (tf32-pre-rounded for pass2)
// =====================================================================
__global__ void reduce_act_kernel(const float* __restrict__ b) {
    int idx = blockIdx.x * blockDim.x + threadIdx.x;
    if (idx >= BATCH * DIM) return;
    float sum = b[idx & (DIM - 1)];
#pragma unroll
    for (int s = 0; s < NSPLIT; ++s)
        sum += g_partial[(size_t)s * BATCH * DIM + idx];
    g_h[idx] = __uint_as_float(to_tf32(sigt(sum)));
}

// =====================================================================
// Pass 2 (tf32 tensor): y = sigmoid(h @ w^T)  [round-7 passing version]
// =====================================================================
__device__ __forceinline__ void p2_load(unsigned hbase, int buf, int ib, int t) {
    const unsigned dst0 = hbase + (unsigned)buf * (P2_MROWS * HS_STRIDE * 4);
#pragma unroll
    for (int i = 0; i < 2; ++i) {
        int e   = i * P2_THREADS + t;
        int row = e >> 3;
        int q   = e & 7;
        cp16(dst0 + (unsigned)(row * HS_STRIDE + q * 4) * 4u,
             &g_h[(size_t)(ib + row) * DIM + q * 4]);
    }
}

__global__ __launch_bounds__(P2_THREADS, 2) void pass2_kernel(const float* __restrict__ W,
                                                              float* __restrict__ Y) {
    __shared__ float hs[2][P2_MROWS * HS_STRIDE];
    const unsigned hbase = smem_u32(&hs[0][0]);

    const int t    = threadIdx.x;
    const int lane = t & 31;
    const int wid  = t >> 5;
    const int wm   = wid & 3;
    const int wn   = wid >> 2;
    const int g    = lane >> 2;
    const int tig  = lane & 3;
    const int c0   = blockIdx.x * P2_COLS + wn * 64;
    const int ib0  = blockIdx.y * (BATCH / P2_YSPLIT);

    uint32_t bw[8][4][2];
#pragma unroll
    for (int nt = 0; nt < 8; ++nt) {
        int j = c0 + nt * 8 + g;
        bool v = (j < VOCAB);
        const float* wr = W + (size_t)(v ? j : 0) * DIM;
#pragma unroll
        for (int ks = 0; ks < 4; ++ks) {
            bw[nt][ks][0] = to_tf32(v ? wr[ks * 8 + tig]     : 0.f);
            bw[nt][ks][1] = to_tf32(v ? wr[ks * 8 + tig + 4] : 0.f);
        }
    }

    p2_load(hbase, 0, ib0, t);
    CP_COMMIT();

    for (int c = 0; c < P2_CHUNKS; ++c) {
        if (c + 1 < P2_CHUNKS) p2_load(hbase, (c + 1) & 1, ib0 + (c + 1) * P2_MROWS, t);
        CP_COMMIT();
        CP_WAIT1();
        __syncthreads();

        const float* hb = hs[c & 1];
        float acc[8][4];
#pragma unroll
        for (int nt = 0; nt < 8; ++nt)
#pragma unroll
            for (int i = 0; i < 4; ++i) acc[nt][i] = 0.f;

#pragma unroll
        for (int ks = 0; ks < 4; ++ks) {
            uint32_t a[4];
            const float* ap = hb + (wm * 16 + g) * HS_STRIDE + ks * 8 + tig;
            a[0] = __float_as_uint(ap[0]);
            a[1] = __float_as_uint(ap[8 * HS_STRIDE]);
            a[2] = __float_as_uint(ap[4]);
            a[3] = __float_as_uint(ap[8 * HS_STRIDE + 4]);
#pragma unroll
            for (int nt = 0; nt < 8; ++nt)
                mma_tf32(acc[nt], a, bw[nt][ks]);
        }

        const size_t r0 = (size_t)(ib0 + c * P2_MROWS + wm * 16 + g);
#pragma unroll
        for (int nt = 0; nt < 8; ++nt) {
            int colb = c0 + nt * 8;
            if (colb < VOCAB) {
                int col = colb + 2 * tig;
                float2 lo = make_float2(sigt(acc[nt][0]), sigt(acc[nt][1]));
                float2 hi = make_float2(sigt(acc[nt][2]), sigt(acc[nt][3]));
                *reinterpret_cast<float2*>(&Y[r0 * VOCAB + col])       = lo;
                *reinterpret_cast<float2*>(&Y[(r0 + 8) * VOCAB + col]) = hi;
            }
        }
        __syncthreads();
    }
}

// =====================================================================
extern "C" void kernel_launch(void* const* d_in, const int* in_sizes, int n_in,
                              void* d_out, int out_size) {
    const float* x = (const float*)d_in[0];  // [4096, 81616]
    const float* w = (const float*)d_in[1];  // [81616, 32]
    const float* b = (const float*)d_in[2];  // [32]
    float* y = (float*)d_out;                // [4096, 81616]

    cudaFuncSetAttribute(pass1_kernel, cudaFuncAttributeMaxDynamicSharedMemorySize, P1_SMEM);

    dim3 g1(ROWBLOCKS, NSPLIT);
    pass1_kernel<<<g1, P1_THREADS, P1_SMEM>>>(x, w);

    reduce_act_kernel<<<(BATCH * DIM + 255) / 256, 256>>>(b);

    dim3 g2((VOCAB + P2_COLS - 1) / P2_COLS, P2_YSPLIT);
    pass2_kernel<<<g2, P2_THREADS>>>(w, y);
}